// round 4
// baseline (speedup 1.0000x reference)
#include <cuda_runtime.h>
#include <cuda_bf16.h>

// AdaptiveTokenMixer: out[b,n,:] = sum_k alpha[b,n,k] * x[b,n+k,:]
// alpha from masked temporal-decay softmax blended with softmax(w), sigmoid(beta).
// Shapes fixed by problem: B=8, N=4096, d=256, K=8.
//
// Design: each thread owns one float4 column of an 8-row strip and loads the
// full 15-row window into registers in ONE front-batched burst (MLP=15),
// then runs a pure-FMA epilogue. No load in the dependent path.

constexpr int K_OFF = 8;     // kernel window
constexpr int D4    = 64;    // d / 4 (float4 columns)
constexpr int RG    = 8;     // rows per thread-group
constexpr int WIN   = RG + K_OFF - 1;  // 15 rows resident in registers
constexpr int G     = 2;     // row-groups per block
constexpr int NR    = RG * G;          // 16 rows per block
constexpr int NTHR  = D4 * G;          // 128 threads

// valid_mask dtype probe (JAX bool may arrive as uint8 / int32 / float32).
// lengths >= N/2 guarantees mask[0..3] of batch 0 are all True:
//   uint8:   byte[1] == 1
//   float32: byte[1] == 0, byte[3] == 0x3f   (1.0f = 00 00 80 3f)
//   int32:   byte[1] == 0, byte[3] == 0x00
__device__ __forceinline__ int probe_mask_mode(const unsigned char* vm) {
    if (vm[1] != 0) return 0;           // uint8
    if (vm[3] == 0x3f) return 2;        // float32
    return 1;                           // int32
}

__device__ __forceinline__ bool mask_at(const unsigned char* vm, int idx, int mode) {
    if (mode == 0) return vm[idx] != 0;
    if (mode == 1) return reinterpret_cast<const int*>(vm)[idx] != 0;
    return reinterpret_cast<const float*>(vm)[idx] != 0.0f;
}

__global__ __launch_bounds__(NTHR, 6) void atm_kernel(
    const float* __restrict__ x,
    const float* __restrict__ dt,
    const unsigned char* __restrict__ vm,
    const float* __restrict__ w,
    const float* __restrict__ beta,
    float* __restrict__ out,
    int N)
{
    __shared__ float s_alpha[NR][K_OFF];

    const int b   = blockIdx.y;
    const int n0  = blockIdx.x * NR;
    const int tid = threadIdx.x;

    // -------- Phase 1: per-row alpha[8] into shared (one thread per row) ------
    if (tid < NR) {
        const int n = n0 + tid;
        const int mmode = probe_mask_mode(vm);
        const float* dtb = dt + (size_t)b * N;
        const int    mb0 = b * N;   // element offset into mask

        // softmax(w) — 8 elems, L1-cached broadcast loads
        float wv[K_OFF];
        #pragma unroll
        for (int k = 0; k < K_OFF; k++) wv[k] = w[k];
        float wm = wv[0];
        #pragma unroll
        for (int k = 1; k < K_OFF; k++) wm = fmaxf(wm, wv[k]);
        float wsum = 0.f;
        #pragma unroll
        for (int k = 0; k < K_OFF; k++) { wv[k] = __expf(wv[k] - wm); wsum += wv[k]; }
        const float winv = 1.f / wsum;
        const float bsig = 1.f / (1.f + __expf(-beta[0]));

        const bool  v0  = mask_at(vm, mb0 + n, mmode);
        const float dtn = dtb[n];

        float sc[K_OFF];
        bool  cv[K_OFF];
        #pragma unroll
        for (int k = 0; k < K_OFF; k++) {
            const int  nk  = n + k;
            const bool inb = (nk < N);
            const int  nks = inb ? nk : n;              // OOB-safe index
            const bool c   = v0 && inb && mask_at(vm, mb0 + nks, mmode);
            const float td = (k == 0) ? 0.f : fmaxf(dtb[nks] - dtn, 0.f);
            cv[k] = c;
            sc[k] = c ? -td : -1e9f;
        }
        float m = sc[0];
        #pragma unroll
        for (int k = 1; k < K_OFF; k++) m = fmaxf(m, sc[k]);
        float th[K_OFF];
        float es = 0.f;
        #pragma unroll
        for (int k = 0; k < K_OFF; k++) { th[k] = __expf(sc[k] - m); es += th[k]; }
        const float einv = 1.f / es;

        float a[K_OFF];
        float asum = 0.f;
        #pragma unroll
        for (int k = 0; k < K_OFF; k++) {
            const float v = bsig * (wv[k] * winv) + (1.f - bsig) * (th[k] * einv);
            a[k] = cv[k] ? v : 0.f;
            asum += a[k];
        }
        const float ainv = 1.f / fmaxf(asum, 1e-8f);
        #pragma unroll
        for (int k = 0; k < K_OFF; k++) s_alpha[tid][k] = a[k] * ainv;
    }

    // -------- Phase 2: full window in registers, front-batched loads ----------
    const int c = tid & (D4 - 1);
    const int g = tid >> 6;                 // log2(D4) = 6
    const int rbase = n0 + g * RG;

    const float4* __restrict__ xcol =
        reinterpret_cast<const float4*>(x) + (size_t)b * N * D4 + c;
    float4* __restrict__ ocol =
        reinterpret_cast<float4*>(out) + (size_t)b * N * D4 + c;

    const float4 zero4 = make_float4(0.f, 0.f, 0.f, 0.f);

    // One batched burst of 15 independent LDG.128 (issued before the barrier
    // so they overlap phase-1 softmax latency too).
    float4 win[WIN];
    #pragma unroll
    for (int k = 0; k < WIN; k++) {
        const int n = rbase + k;
        win[k] = (n < N) ? xcol[(size_t)n * D4] : zero4;
    }

    __syncthreads();   // s_alpha ready

    #pragma unroll
    for (int r = 0; r < RG; r++) {
        const float* al = s_alpha[g * RG + r];
        float4 acc = zero4;
        #pragma unroll
        for (int k = 0; k < K_OFF; k++) {
            const float  a = al[k];
            const float4 v = win[r + k];
            acc.x = fmaf(a, v.x, acc.x);
            acc.y = fmaf(a, v.y, acc.y);
            acc.z = fmaf(a, v.z, acc.z);
            acc.w = fmaf(a, v.w, acc.w);
        }
        ocol[(size_t)(rbase + r) * D4] = acc;
    }
}

extern "C" void kernel_launch(void* const* d_in, const int* in_sizes, int n_in,
                              void* d_out, int out_size)
{
    // metadata order: x [B,N,d] f32, delta_times [B,N] f32, valid_mask [B,N],
    //                 w [8] f32, beta [1] f32 ; output [B,N,d] f32
    const float*         x    = (const float*)d_in[0];
    const float*         dt   = (const float*)d_in[1];
    const unsigned char* vm   = (const unsigned char*)d_in[2];
    const float*         w    = (const float*)d_in[3];
    const float*         beta = (const float*)d_in[4];
    float*               out  = (float*)d_out;

    const int N = 4096;                       // fixed by problem
    const int BN = in_sizes[1];               // B*N
    const int B = BN / N;                     // 8

    dim3 grid((N + NR - 1) / NR, B);
    atm_kernel<<<grid, NTHR>>>(x, dt, vm, w, beta, out, N);
}

// round 5
// speedup vs baseline: 1.1325x; 1.1325x over previous
#include <cuda_runtime.h>
#include <cuda_bf16.h>

// AdaptiveTokenMixer: out[b,n,:] = sum_k alpha[b,n,k] * x[b,n+k,:]
// Shapes fixed: B=8, N=4096, d=256, K=8.
//
// R5 design: RG=16 rows/thread (amp 1.44x), rolling register ring of depth 10
// (prefetch distance = 3 iterations to cover ~234cyc L2 hit latency),
// alpha rows read as 2x LDS.128, prefill overlapped with phase-1 softmax.

constexpr int K_OFF = 8;     // kernel window
constexpr int D4    = 64;    // d / 4 (float4 columns)
constexpr int RG    = 16;    // rows per thread-group
constexpr int RING  = 10;    // register ring depth (K_OFF + prefetch 2)
constexpr int G     = 2;     // row-groups per block
constexpr int NR    = RG * G;          // 32 rows per block
constexpr int NTHR  = D4 * G;          // 128 threads

// valid_mask dtype probe (JAX bool may arrive as uint8 / int32 / float32).
// lengths >= N/2 guarantees mask[0..3] of batch 0 are all True:
//   uint8:   byte[1] == 1
//   float32: byte[1] == 0, byte[3] == 0x3f   (1.0f = 00 00 80 3f)
//   int32:   byte[1] == 0, byte[3] == 0x00
__device__ __forceinline__ int probe_mask_mode(const unsigned char* vm) {
    if (vm[1] != 0) return 0;           // uint8
    if (vm[3] == 0x3f) return 2;        // float32
    return 1;                           // int32
}

__device__ __forceinline__ bool mask_at(const unsigned char* vm, int idx, int mode) {
    if (mode == 0) return vm[idx] != 0;
    if (mode == 1) return reinterpret_cast<const int*>(vm)[idx] != 0;
    return reinterpret_cast<const float*>(vm)[idx] != 0.0f;
}

__global__ __launch_bounds__(NTHR, 7) void atm_kernel(
    const float* __restrict__ x,
    const float* __restrict__ dt,
    const unsigned char* __restrict__ vm,
    const float* __restrict__ w,
    const float* __restrict__ beta,
    float* __restrict__ out,
    int N)
{
    __shared__ float4 s_alpha[NR][2];    // 8 alphas per row as two float4

    const int b   = blockIdx.y;
    const int n0  = blockIdx.x * NR;
    const int tid = threadIdx.x;

    // -------- Phase 2 setup + prefill (issued BEFORE phase-1 to overlap) -----
    const int c = tid & (D4 - 1);
    const int g = tid >> 6;                 // log2(D4) = 6
    const int rbase = n0 + g * RG;

    const float4* __restrict__ xcol =
        reinterpret_cast<const float4*>(x) + (size_t)b * N * D4 + c;
    float4* __restrict__ ocol =
        reinterpret_cast<float4*>(out) + (size_t)b * N * D4 + c;

    const float4 zero4 = make_float4(0.f, 0.f, 0.f, 0.f);
    float4 win[RING];
    #pragma unroll
    for (int k = 0; k < RING; k++) {
        const int n = rbase + k;
        win[k] = (n < N) ? xcol[(size_t)n * D4] : zero4;
    }

    // -------- Phase 1: per-row alpha[8] into shared (one thread per row) ------
    if (tid < NR) {
        const int n = n0 + tid;
        const int mmode = probe_mask_mode(vm);
        const float* dtb = dt + (size_t)b * N;
        const int    mb0 = b * N;   // element offset into mask

        // softmax(w) — 8 elems, L1-cached broadcast loads
        float wv[K_OFF];
        #pragma unroll
        for (int k = 0; k < K_OFF; k++) wv[k] = w[k];
        float wm = wv[0];
        #pragma unroll
        for (int k = 1; k < K_OFF; k++) wm = fmaxf(wm, wv[k]);
        float wsum = 0.f;
        #pragma unroll
        for (int k = 0; k < K_OFF; k++) { wv[k] = __expf(wv[k] - wm); wsum += wv[k]; }
        const float winv = 1.f / wsum;
        const float bsig = 1.f / (1.f + __expf(-beta[0]));

        const bool  v0  = mask_at(vm, mb0 + n, mmode);
        const float dtn = dtb[n];

        float sc[K_OFF];
        bool  cv[K_OFF];
        #pragma unroll
        for (int k = 0; k < K_OFF; k++) {
            const int  nk  = n + k;
            const bool inb = (nk < N);
            const int  nks = inb ? nk : n;              // OOB-safe index
            const bool cnd = v0 && inb && mask_at(vm, mb0 + nks, mmode);
            const float td = (k == 0) ? 0.f : fmaxf(dtb[nks] - dtn, 0.f);
            cv[k] = cnd;
            sc[k] = cnd ? -td : -1e9f;
        }
        float m = sc[0];
        #pragma unroll
        for (int k = 1; k < K_OFF; k++) m = fmaxf(m, sc[k]);
        float th[K_OFF];
        float es = 0.f;
        #pragma unroll
        for (int k = 0; k < K_OFF; k++) { th[k] = __expf(sc[k] - m); es += th[k]; }
        const float einv = 1.f / es;

        float a[K_OFF];
        float asum = 0.f;
        #pragma unroll
        for (int k = 0; k < K_OFF; k++) {
            const float v = bsig * (wv[k] * winv) + (1.f - bsig) * (th[k] * einv);
            a[k] = cv[k] ? v : 0.f;
            asum += a[k];
        }
        const float ainv = 1.f / fmaxf(asum, 1e-8f);
        #pragma unroll
        for (int k = 0; k < K_OFF; k++) a[k] *= ainv;
        s_alpha[tid][0] = make_float4(a[0], a[1], a[2], a[3]);
        s_alpha[tid][1] = make_float4(a[4], a[5], a[6], a[7]);
    }
    __syncthreads();

    // -------- Phase 2: rolling ring, prefetch distance 3 iterations ----------
    #pragma unroll
    for (int r = 0; r < RG; r++) {
        const int row = g * RG + r;
        const float4 a03 = s_alpha[row][0];
        const float4 a47 = s_alpha[row][1];
        const float al[K_OFF] = { a03.x, a03.y, a03.z, a03.w,
                                  a47.x, a47.y, a47.z, a47.w };

        float4 acc = zero4;
        #pragma unroll
        for (int k = 0; k < K_OFF; k++) {
            const float  a = al[k];
            const float4 v = win[(r + k) % RING];
            acc.x = fmaf(a, v.x, acc.x);
            acc.y = fmaf(a, v.y, acc.y);
            acc.z = fmaf(a, v.z, acc.z);
            acc.w = fmaf(a, v.w, acc.w);
        }
        ocol[(size_t)(rbase + r) * D4] = acc;

        // Refill: row rbase+r+RING into the slot just vacated (consumed at k=0).
        if (r + RING < RG + K_OFF - 1) {
            const int nl = rbase + r + RING;
            win[r % RING] = (nl < N) ? xcol[(size_t)nl * D4] : zero4;
        }
    }
}

extern "C" void kernel_launch(void* const* d_in, const int* in_sizes, int n_in,
                              void* d_out, int out_size)
{
    // metadata order: x [B,N,d] f32, delta_times [B,N] f32, valid_mask [B,N],
    //                 w [8] f32, beta [1] f32 ; output [B,N,d] f32
    const float*         x    = (const float*)d_in[0];
    const float*         dt   = (const float*)d_in[1];
    const unsigned char* vm   = (const unsigned char*)d_in[2];
    const float*         w    = (const float*)d_in[3];
    const float*         beta = (const float*)d_in[4];
    float*               out  = (float*)d_out;

    const int N = 4096;                       // fixed by problem
    const int BN = in_sizes[1];               // B*N
    const int B = BN / N;                     // 8

    dim3 grid((N + NR - 1) / NR, B);
    atm_kernel<<<grid, NTHR>>>(x, dt, vm, w, beta, out, N);
}